// round 9
// baseline (speedup 1.0000x reference)
#include <cuda_runtime.h>
#include <cuda_fp16.h>
#include <cstdint>
#include <math.h>

// ---------------------------------------------------------------------------
// Problem constants
// ---------------------------------------------------------------------------
#define P_DIM    4354
#define P_PAD    4416          // 138 * 32  (k padding)
#define MT_TILES 274           // m16 tiles over output p (only real rows)
#define KS_TILES 276           // k16 tiles over input q (padded)
#define KP_TILES 138           // k32 pairs
#define BATCH    32
#define SEQ      64
#define NCTA_MV  137
#define NCTA_MLP 2
#define NCTA     (NCTA_MV + NCTA_MLP)
#define THREADS  512
#define LO_SCALE 2048.0f
#define INV_LO   (1.0f/2048.0f)

// ---------------------------------------------------------------------------
// Static device state (all .bss -> zero-initialized at module load)
// ---------------------------------------------------------------------------
// E = A - I, double-fp16 split, m16n8k16 A-fragment order:
//   uint4 slot [(mt*KS_TILES + ks)*32 + lane] = halfs a0..a7
__device__ __align__(16) __half E_hi[(size_t)MT_TILES * KS_TILES * 256];
__device__ __align__(16) __half E_lo[(size_t)MT_TILES * KS_TILES * 256];

// theta double-fp16 split, m16n8k16 B-fragment order, double buffered:
//   half [(((kp*4 + nb)*32 + lane)*8 + j];  j0..3 -> k-tile 2kp, j4..7 -> 2kp+1
__device__ __align__(16) __half Tf_hi[2][KP_TILES * 4 * 32 * 8];
__device__ __align__(16) __half Tf_lo[2][KP_TILES * 4 * 32 * 8];

// theta fp32 [b][p] (stride P_PAD), double buffered (exact path for MLP)
__device__ __align__(16) float theta_f[2][BATCH * P_PAD];

__device__ float dx_g[BATCH];
__device__ unsigned int g_arrive;   // monotonic barrier counter (reset per launch)

// ---------------------------------------------------------------------------
__device__ __forceinline__ void grid_sync(unsigned target) {
    __syncthreads();
    if (threadIdx.x == 0) {
        unsigned* p = &g_arrive;
        asm volatile("red.release.gpu.global.add.u32 [%0], 1;" :: "l"(p) : "memory");
        unsigned v;
        do {
            asm volatile("ld.acquire.gpu.global.u32 %0, [%1];" : "=r"(v) : "l"(p) : "memory");
        } while (v < target);
    }
    __syncthreads();
}

__device__ __forceinline__ void mma16816(float c[4], const uint4& a,
                                         unsigned b0, unsigned b1) {
    asm volatile(
        "mma.sync.aligned.m16n8k16.row.col.f32.f16.f16.f32 "
        "{%0,%1,%2,%3}, {%4,%5,%6,%7}, {%8,%9}, {%0,%1,%2,%3};\n"
        : "+f"(c[0]), "+f"(c[1]), "+f"(c[2]), "+f"(c[3])
        : "r"(a.x), "r"(a.y), "r"(a.z), "r"(a.w), "r"(b0), "r"(b1));
}

// ---------------------------------------------------------------------------
// Setup 1: E = A - I  ->  hi/lo fp16 split in A-fragment layout
// ---------------------------------------------------------------------------
__global__ void build_E_kernel(const float* __restrict__ A) {
    size_t i = (size_t)blockIdx.x * blockDim.x + threadIdx.x; // uint4 slot
    const size_t total = (size_t)MT_TILES * KS_TILES * 32;
    if (i >= total) return;
    int lane = (int)(i & 31);
    size_t tile = i >> 5;
    int ks = (int)(tile % KS_TILES);
    int mt = (int)(tile / KS_TILES);
    int r  = lane >> 2;
    int c2 = (lane & 3) * 2;
    int ps[2] = { mt * 16 + r, mt * 16 + r + 8 };
    int qs[4] = { ks * 16 + c2, ks * 16 + c2 + 1, ks * 16 + c2 + 8, ks * 16 + c2 + 9 };
    const int ord_p[8] = {0,0,1,1,0,0,1,1};
    const int ord_q[8] = {0,1,0,1,2,3,2,3};
    __align__(16) __half hh[8];
    __align__(16) __half hl[8];
#pragma unroll
    for (int j = 0; j < 8; ++j) {
        int p = ps[ord_p[j]], q = qs[ord_q[j]];
        float v = 0.f;
        if (p < P_DIM && q < P_DIM)
            v = A[(size_t)p * P_DIM + q] - ((p == q) ? 1.f : 0.f);
        __half h = __float2half(v);
        hh[j] = h;
        hl[j] = __float2half((v - __half2float(h)) * LO_SCALE);
    }
    ((uint4*)E_hi)[i] = *(const uint4*)hh;
    ((uint4*)E_lo)[i] = *(const uint4*)hl;
}

// ---------------------------------------------------------------------------
// Setup 2: init theta buffers + reset barrier.  BATCH*P_PAD == KP*4*32*8.
// ---------------------------------------------------------------------------
__global__ void init_state_kernel(const float* __restrict__ theta_init) {
    int i = blockIdx.x * blockDim.x + threadIdx.x;
    if (i == 0) g_arrive = 0u;
    if (i >= BATCH * P_PAD) return;
    int p = i % P_PAD;
    theta_f[0][i] = (p < P_DIM) ? theta_init[p] : 0.f;

    // fragment slot -> k index (value independent of n)
    int jj   = i & 7;
    int lane = (i >> 3) & 31;
    int kp   = i >> 10;
    int tig  = lane & 3;
    int k = kp * 32 + ((jj & 4) ? 16 : 0) + 2 * tig
          + (((jj & 3) >= 2) ? 8 : 0) + (jj & 1);
    float v = (k < P_DIM) ? theta_init[k] : 0.f;
    __half h = __float2half(v);
    Tf_hi[0][i] = h;
    Tf_lo[0][i] = __float2half((v - __half2float(h)) * LO_SCALE);
}

// ---------------------------------------------------------------------------
// Main persistent kernel: 137 matvec CTAs + 2 MLP CTAs, 512 threads each
// ---------------------------------------------------------------------------
__global__ void __launch_bounds__(THREADS, 1)
main_kernel(const float* __restrict__ xs, const float* __restrict__ noise,
            const float* __restrict__ theta_init, const float* __restrict__ Bvec,
            const int* __restrict__ p_is, int has_is, float* __restrict__ out)
{
    const int cta  = blockIdx.x;
    const int tid  = threadIdx.x;
    const int w    = tid >> 5;
    const int lane = tid & 31;
    const unsigned NB = gridDim.x;
    const int inf_start = has_is ? __ldg(p_is) : 32;
    unsigned ns = 0;   // sync serial number

    __shared__ float red[3][4][32][8];   // combined partials from kq 1..3

    if (cta < NCTA_MV) {
        // =============================== MATVEC ===============================
        const int nb = w & 3;        // n-block (8 batch columns)
        const int kq = w >> 2;       // k-quarter
        const int mt0 = cta * 2;
        const int kp0 = (kq * KP_TILES) >> 2;
        const int kp1 = ((kq + 1) * KP_TILES) >> 2;
        const int row = lane >> 2;
        const int c2  = (lane & 3) * 2;

        int   pvals[4];
        float Bp[4];
        float tprev[8];
#pragma unroll
        for (int mt = 0; mt < 2; ++mt)
#pragma unroll
            for (int hhh = 0; hhh < 2; ++hhh) {
                int p = (mt0 + mt) * 16 + row + hhh * 8;
                pvals[mt * 2 + hhh] = p;
                Bp[mt * 2 + hhh] = (p < P_DIM) ? __ldg(Bvec + p) : 0.f;
            }
#pragma unroll
        for (int j = 0; j < 8; ++j) {
            int mt = j >> 2, cj = j & 3;
            int p = pvals[mt * 2 + ((cj >> 1) & 1)];
            tprev[j] = (p < P_DIM) ? __ldg(theta_init + p) : 0.f;
        }

        const uint4* EH = ((const uint4*)E_hi) + ((size_t)mt0 * KS_TILES) * 32 + lane;
        const uint4* EL = ((const uint4*)E_lo) + ((size_t)mt0 * KS_TILES) * 32 + lane;

        for (int t = 0; t < SEQ - 1; ++t) {
            const int cur = t & 1, nxt = cur ^ 1;

            float a0h[4] = {0,0,0,0}, a1h[4] = {0,0,0,0};
            float a0l[4] = {0,0,0,0}, a1l[4] = {0,0,0,0};
            {
                const uint4* Th = ((const uint4*)Tf_hi[cur]) + nb * 32 + lane;
                const uint4* Tl = ((const uint4*)Tf_lo[cur]) + nb * 32 + lane;
#pragma unroll 1
                for (int kp = kp0; kp < kp1; ++kp) {
                    // all 10 loads issue up front; 16 warps/SM cover L2 latency
                    uint4 th  = __ldcg(Th + (size_t)kp * 128);
                    uint4 tl  = __ldcg(Tl + (size_t)kp * 128);
                    uint4 eh0 = __ldg(EH + (size_t)(2*kp)*32);
                    uint4 eh1 = __ldg(EH + (size_t)(2*kp+1)*32);
                    uint4 eh2 = __ldg(EH + (size_t)(KS_TILES + 2*kp)*32);
                    uint4 eh3 = __ldg(EH + (size_t)(KS_TILES + 2*kp+1)*32);
                    uint4 el0 = __ldg(EL + (size_t)(2*kp)*32);
                    uint4 el1 = __ldg(EL + (size_t)(2*kp+1)*32);
                    uint4 el2 = __ldg(EL + (size_t)(KS_TILES + 2*kp)*32);
                    uint4 el3 = __ldg(EL + (size_t)(KS_TILES + 2*kp+1)*32);
                    // hi(E)*hi(theta)
                    mma16816(a0h, eh0, th.x, th.y);
                    mma16816(a0h, eh1, th.z, th.w);
                    mma16816(a1h, eh2, th.x, th.y);
                    mma16816(a1h, eh3, th.z, th.w);
                    // lo(E)*hi(theta)
                    mma16816(a0l, el0, th.x, th.y);
                    mma16816(a0l, el1, th.z, th.w);
                    mma16816(a1l, el2, th.x, th.y);
                    mma16816(a1l, el3, th.z, th.w);
                    // hi(E)*lo(theta)
                    mma16816(a0l, eh0, tl.x, tl.y);
                    mma16816(a0l, eh1, tl.z, tl.w);
                    mma16816(a1l, eh2, tl.x, tl.y);
                    mma16816(a1l, eh3, tl.z, tl.w);
                }
            }
            // combine splits in fp32
            float c0[4], c1[4];
#pragma unroll
            for (int j = 0; j < 4; ++j) {
                c0[j] = a0h[j] + a0l[j] * INV_LO;
                c1[j] = a1h[j] + a1l[j] * INV_LO;
            }
            if (kq) {
#pragma unroll
                for (int j = 0; j < 4; ++j) {
                    red[kq - 1][nb][lane][j]     = c0[j];
                    red[kq - 1][nb][lane][4 + j] = c1[j];
                }
            }

            grid_sync(++ns * NB);   // acc partials + dx ready

            if (kq == 0) {
#pragma unroll
                for (int q = 0; q < 3; ++q)
#pragma unroll
                    for (int j = 0; j < 4; ++j) {
                        c0[j] += red[q][nb][lane][j];
                        c1[j] += red[q][nb][lane][4 + j];
                    }
                int b0 = nb * 8 + c2;
                float dxa = __ldcv(dx_g + b0);
                float dxb = __ldcv(dx_g + b0 + 1);
#pragma unroll
                for (int j = 0; j < 8; ++j) {
                    int mt = j >> 2, cj = j & 3;
                    float acc = mt ? c1[cj] : c0[cj];
                    int hhh = (cj >> 1) & 1;
                    int p = pvals[mt * 2 + hhh];
                    int b = b0 + (cj & 1);
                    float v = tprev[j] + acc + ((cj & 1) ? dxb : dxa) * Bp[mt * 2 + hhh];
                    v = fminf(1.f, fmaxf(-1.f, v));
                    tprev[j] = v;
                    theta_f[nxt][(size_t)b * P_PAD + p] = v;
                    // scatter into B-fragment layout (hi/lo)
                    int koff = p & 31, k16 = koff & 15;
                    int jj   = ((koff >> 4) << 2) | ((k16 >> 3) << 1) | (k16 & 1);
                    int tig  = (k16 & 7) >> 1;
                    int lane2 = ((b & 7) << 2) | tig;
                    size_t idx = ((size_t)((p >> 5) * 4 + (b >> 3)) * 32 + lane2) * 8 + jj;
                    __half hv = __float2half(v);
                    Tf_hi[nxt][idx] = hv;
                    Tf_lo[nxt][idx] = __float2half((v - __half2float(hv)) * LO_SCALE);
                }
            }

            grid_sync(++ns * NB);   // theta_{t+1} published
        }
    } else {
        // ================================ MLP =================================
        const int bat = (cta - NCTA_MV) * 16 + w;   // warp = one batch element
        float x_prev = 0.f;                          // lane 0 state

        for (int t = 0; t < SEQ; ++t) {
            const int cur = t & 1;
            const float* th = theta_f[cur] + (size_t)bat * P_PAD;
            float tt = (float)t * (1.0f / (float)SEQ);

            // layer 0: 1 -> 32
            float z = tt * __ldcg(th + lane) + __ldcg(th + 32 + lane);
            float y = z / (1.f + expf(-z));

            // layers 1..4: 32 -> 32 (lane owns output row)
#pragma unroll
            for (int L = 0; L < 4; ++L) {
                const float* Wb = th + 64 + L * 1056;
                const float4* rp = (const float4*)(Wb + lane * 32);
                float4 wr[8];
#pragma unroll
                for (int j = 0; j < 8; ++j) wr[j] = __ldcg(rp + j);
                float acc = __ldcg(Wb + 1024 + lane);
#pragma unroll
                for (int j = 0; j < 8; ++j) {
                    acc += __shfl_sync(0xffffffffu, y, 4*j + 0) * wr[j].x;
                    acc += __shfl_sync(0xffffffffu, y, 4*j + 1) * wr[j].y;
                    acc += __shfl_sync(0xffffffffu, y, 4*j + 2) * wr[j].z;
                    acc += __shfl_sync(0xffffffffu, y, 4*j + 3) * wr[j].w;
                }
                y = acc / (1.f + expf(-acc));
            }

            // final layer: 32 -> 2
            const float* Wf = th + 4288;
            float pm = y * __ldcg(Wf + lane);
            float pv = y * __ldcg(Wf + 32 + lane);
#pragma unroll
            for (int off = 16; off; off >>= 1) {
                pm += __shfl_xor_sync(0xffffffffu, pm, off);
                pv += __shfl_xor_sync(0xffffffffu, pv, off);
            }
            if (lane == 0) {
                float meanv = tanhf(pm + __ldcg(Wf + 64));
                float lv = pv + __ldcg(Wf + 65);
                lv = fminf(4.f, fmaxf(-4.f, lv));
                float stdv = expf(0.5f * lv);
                out[bat * SEQ + t] = meanv;                 // means.T
                out[BATCH * SEQ + bat * SEQ + t] = stdv;    // stds.T
                float x_t = (t < inf_start)
                    ? __ldg(xs + bat * SEQ + t)
                    : fmaf(__ldg(noise + t * BATCH + bat), stdv, meanv);
                dx_g[bat] = x_t - x_prev;
                x_prev = x_t;
            }

            if (t == SEQ - 1) break;
            grid_sync(++ns * NB);
            grid_sync(++ns * NB);
        }
    }
}

// ---------------------------------------------------------------------------
extern "C" void kernel_launch(void* const* d_in, const int* in_sizes, int n_in,
                              void* d_out, int out_size) {
    const float* xs         = (const float*)d_in[0];
    const float* noise      = (const float*)d_in[1];
    const float* theta_init = (const float*)d_in[2];
    const float* A          = (const float*)d_in[3];
    const float* Bv         = (const float*)d_in[4];
    const int*   p_is       = (n_in > 5) ? (const int*)d_in[5] : nullptr;
    const int    has_is     = (n_in > 5) ? 1 : 0;

    const long long tot = (long long)MT_TILES * KS_TILES * 32;
    build_E_kernel<<<(int)((tot + 255) / 256), 256>>>(A);
    init_state_kernel<<<(BATCH * P_PAD + 255) / 256, 256>>>(theta_init);
    main_kernel<<<NCTA, THREADS>>>(xs, noise, theta_init, Bv, p_is, has_is,
                                   (float*)d_out);
}

// round 17
// speedup vs baseline: 1.0350x; 1.0350x over previous
#include <cuda_runtime.h>
#include <cuda_fp16.h>
#include <cstdint>
#include <math.h>

// ---------------------------------------------------------------------------
// Problem constants
// ---------------------------------------------------------------------------
#define P_DIM    4354
#define P_PAD    4416          // 138 * 32  (k padding)
#define MT_TILES 274           // m16 tiles over output p
#define KS_TILES 276           // k16 tiles over input q (padded)
#define KP_TILES 138           // k32 pairs
#define BATCH    32
#define SEQ      64
#define NCTA_MV  137
#define NCTA_MLP 2
#define NCTA     (NCTA_MV + NCTA_MLP)
#define THREADS  512
#define LO_SCALE 2048.0f
#define INV_LO   (1.0f/2048.0f)
#define E_SLOTS  ((size_t)MT_TILES * KS_TILES * 32)   // uint4 fragments

// ---------------------------------------------------------------------------
// Static device state (.bss zero at module load; counters reset per launch
// by reset_kernel, stream-ordered BEFORE the persistent kernel)
// ---------------------------------------------------------------------------
__device__ __align__(16) __half E_hi[(size_t)MT_TILES * KS_TILES * 256];
__device__ __align__(16) __half E_lo[(size_t)MT_TILES * KS_TILES * 256];
__device__ __align__(16) __half Tf_hi[2][KP_TILES * 4 * 32 * 8];
__device__ __align__(16) __half Tf_lo[2][KP_TILES * 4 * 32 * 8];
__device__ __align__(16) float theta_f[2][BATCH * P_PAD];
__device__ float dx_g[BATCH];
__device__ unsigned int g_arrive;   // monotonic grid barrier counter
__device__ unsigned int mlp_flag;   // monotonic dx-ready flag (2 per step)

// ---------------------------------------------------------------------------
__global__ void reset_kernel() {
    if (threadIdx.x == 0) {
        g_arrive = 0u;
        mlp_flag = 0u;
    }
}

// ---------------------------------------------------------------------------
__device__ __forceinline__ void grid_sync(unsigned target) {
    __syncthreads();
    if (threadIdx.x == 0) {
        unsigned* p = &g_arrive;
        asm volatile("red.release.gpu.global.add.u32 [%0], 1;" :: "l"(p) : "memory");
        unsigned v;
        do {
            asm volatile("ld.acquire.gpu.global.u32 %0, [%1];" : "=r"(v) : "l"(p) : "memory");
        } while ((int)(v - target) < 0);
    }
    __syncthreads();
}

__device__ __forceinline__ void mma16816(float c[4], const uint4& a,
                                         unsigned b0, unsigned b1) {
    asm volatile(
        "mma.sync.aligned.m16n8k16.row.col.f32.f16.f16.f32 "
        "{%0,%1,%2,%3}, {%4,%5,%6,%7}, {%8,%9}, {%0,%1,%2,%3};\n"
        : "+f"(c[0]), "+f"(c[1]), "+f"(c[2]), "+f"(c[3])
        : "r"(a.x), "r"(a.y), "r"(a.z), "r"(a.w), "r"(b0), "r"(b1));
}

// ---------------------------------------------------------------------------
// Single persistent kernel: phase0 setup -> 63-step recurrence
// ---------------------------------------------------------------------------
__global__ void __launch_bounds__(THREADS, 1)
main_kernel(const float* __restrict__ xs, const float* __restrict__ noise,
            const float* __restrict__ theta_init, const float* __restrict__ A,
            const float* __restrict__ Bvec,
            const int* __restrict__ p_is, int has_is, float* __restrict__ out)
{
    const int cta  = blockIdx.x;
    const int tid  = threadIdx.x;
    const int w    = tid >> 5;
    const int lane = tid & 31;
    const unsigned NB = NCTA;
    const int inf_start = has_is ? __ldg(p_is) : 32;
    unsigned ns = 0;

    // ===================== phase 0: build E + init state ======================
    {
        const size_t gt = (size_t)cta * THREADS + tid;
        const size_t gs = (size_t)NCTA * THREADS;
        const int ord_p[8] = {0,0,1,1,0,0,1,1};
        const int ord_q[8] = {0,1,0,1,2,3,2,3};
        for (size_t i = gt; i < E_SLOTS; i += gs) {
            int l2  = (int)(i & 31);
            size_t tile = i >> 5;
            int ks = (int)(tile % KS_TILES);
            int mt = (int)(tile / KS_TILES);
            int r  = l2 >> 2;
            int c2 = (l2 & 3) * 2;
            int ps[2] = { mt * 16 + r, mt * 16 + r + 8 };
            int qs[4] = { ks * 16 + c2, ks * 16 + c2 + 1,
                          ks * 16 + c2 + 8, ks * 16 + c2 + 9 };
            __align__(16) __half hh[8];
            __align__(16) __half hl[8];
#pragma unroll
            for (int j = 0; j < 8; ++j) {
                int p = ps[ord_p[j]], q = qs[ord_q[j]];
                float v = 0.f;
                if (p < P_DIM && q < P_DIM)
                    v = __ldg(A + (size_t)p * P_DIM + q) - ((p == q) ? 1.f : 0.f);
                __half h = __float2half(v);
                hh[j] = h;
                hl[j] = __float2half((v - __half2float(h)) * LO_SCALE);
            }
            ((uint4*)E_hi)[i] = *(const uint4*)hh;
            ((uint4*)E_lo)[i] = *(const uint4*)hl;
        }
        for (size_t i = gt; i < (size_t)BATCH * P_PAD; i += gs) {
            int p = (int)(i % P_PAD);
            theta_f[0][i] = (p < P_DIM) ? __ldg(theta_init + p) : 0.f;
            int jj   = (int)(i & 7);
            int l2   = (int)((i >> 3) & 31);
            int kp   = (int)(i >> 10);
            int tig  = l2 & 3;
            int k = kp * 32 + ((jj & 4) ? 16 : 0) + 2 * tig
                  + (((jj & 3) >= 2) ? 8 : 0) + (jj & 1);
            float v = (k < P_DIM) ? __ldg(theta_init + k) : 0.f;
            __half h = __float2half(v);
            Tf_hi[0][i] = h;
            Tf_lo[0][i] = __float2half((v - __half2float(h)) * LO_SCALE);
        }
    }
    grid_sync(++ns * NB);   // E + theta_0 published

    __shared__ float red[3][4][32][8];

    if (cta < NCTA_MV) {
        // =============================== MATVEC ===============================
        const int nb = w & 3;
        const int kq = w >> 2;
        const int mt0 = cta * 2;
        const int kp0 = (kq * KP_TILES) >> 2;
        const int kp1 = ((kq + 1) * KP_TILES) >> 2;
        const int row = lane >> 2;
        const int c2  = (lane & 3) * 2;

        int   pvals[4];
        float Bp[4];
        float tprev[8];
#pragma unroll
        for (int mt = 0; mt < 2; ++mt)
#pragma unroll
            for (int hhh = 0; hhh < 2; ++hhh) {
                int p = (mt0 + mt) * 16 + row + hhh * 8;
                pvals[mt * 2 + hhh] = p;
                Bp[mt * 2 + hhh] = (p < P_DIM) ? __ldg(Bvec + p) : 0.f;
            }
#pragma unroll
        for (int j = 0; j < 8; ++j) {
            int mt = j >> 2, cj = j & 3;
            int p = pvals[mt * 2 + ((cj >> 1) & 1)];
            tprev[j] = (p < P_DIM) ? __ldg(theta_init + p) : 0.f;
        }

        const uint4* EH = ((const uint4*)E_hi) + ((size_t)mt0 * KS_TILES) * 32 + lane;
        const uint4* EL = ((const uint4*)E_lo) + ((size_t)mt0 * KS_TILES) * 32 + lane;

        for (int t = 0; t < SEQ - 1; ++t) {
            const int cur = t & 1, nxt = cur ^ 1;

            float a0h[4] = {0,0,0,0}, a1h[4] = {0,0,0,0};
            float a0l[4] = {0,0,0,0}, a1l[4] = {0,0,0,0};
            {
                const uint4* Th = ((const uint4*)Tf_hi[cur]) + nb * 32 + lane;
                const uint4* Tl = ((const uint4*)Tf_lo[cur]) + nb * 32 + lane;
#pragma unroll 1
                for (int kp = kp0; kp < kp1; ++kp) {
                    uint4 th  = __ldcg(Th + (size_t)kp * 128);
                    uint4 tl  = __ldcg(Tl + (size_t)kp * 128);
                    uint4 eh0 = __ldg(EH + (size_t)(2*kp)*32);
                    uint4 eh1 = __ldg(EH + (size_t)(2*kp+1)*32);
                    uint4 eh2 = __ldg(EH + (size_t)(KS_TILES + 2*kp)*32);
                    uint4 eh3 = __ldg(EH + (size_t)(KS_TILES + 2*kp+1)*32);
                    uint4 el0 = __ldg(EL + (size_t)(2*kp)*32);
                    uint4 el1 = __ldg(EL + (size_t)(2*kp+1)*32);
                    uint4 el2 = __ldg(EL + (size_t)(KS_TILES + 2*kp)*32);
                    uint4 el3 = __ldg(EL + (size_t)(KS_TILES + 2*kp+1)*32);
                    mma16816(a0h, eh0, th.x, th.y);
                    mma16816(a0h, eh1, th.z, th.w);
                    mma16816(a1h, eh2, th.x, th.y);
                    mma16816(a1h, eh3, th.z, th.w);
                    mma16816(a0l, el0, th.x, th.y);
                    mma16816(a0l, el1, th.z, th.w);
                    mma16816(a1l, el2, th.x, th.y);
                    mma16816(a1l, el3, th.z, th.w);
                    mma16816(a0l, eh0, tl.x, tl.y);
                    mma16816(a0l, eh1, tl.z, tl.w);
                    mma16816(a1l, eh2, tl.x, tl.y);
                    mma16816(a1l, eh3, tl.z, tl.w);
                }
            }
            float c0[4], c1[4];
#pragma unroll
            for (int j = 0; j < 4; ++j) {
                c0[j] = a0h[j] + a0l[j] * INV_LO;
                c1[j] = a1h[j] + a1l[j] * INV_LO;
            }
            if (kq) {
#pragma unroll
                for (int j = 0; j < 4; ++j) {
                    red[kq - 1][nb][lane][j]     = c0[j];
                    red[kq - 1][nb][lane][4 + j] = c1[j];
                }
            }

            // intra-CTA: red[] ready; cross-CTA: wait only for dx (not full grid)
            __syncthreads();
            if (tid == 0) {
                const unsigned dxt = 2u * (unsigned)(t + 1);
                unsigned* fp = &mlp_flag;
                unsigned v;
                do {
                    asm volatile("ld.acquire.gpu.global.u32 %0, [%1];"
                                 : "=r"(v) : "l"(fp) : "memory");
                } while ((int)(v - dxt) < 0);
            }
            __syncthreads();

            if (kq == 0) {
#pragma unroll
                for (int q = 0; q < 3; ++q)
#pragma unroll
                    for (int j = 0; j < 4; ++j) {
                        c0[j] += red[q][nb][lane][j];
                        c1[j] += red[q][nb][lane][4 + j];
                    }
                int b0 = nb * 8 + c2;
                float dxa = __ldcg(dx_g + b0);
                float dxb = __ldcg(dx_g + b0 + 1);
#pragma unroll
                for (int j = 0; j < 8; ++j) {
                    int mt = j >> 2, cj = j & 3;
                    float acc = mt ? c1[cj] : c0[cj];
                    int hhh = (cj >> 1) & 1;
                    int p = pvals[mt * 2 + hhh];
                    int b = b0 + (cj & 1);
                    float v = tprev[j] + acc + ((cj & 1) ? dxb : dxa) * Bp[mt * 2 + hhh];
                    v = fminf(1.f, fmaxf(-1.f, v));
                    tprev[j] = v;
                    theta_f[nxt][(size_t)b * P_PAD + p] = v;
                    int koff = p & 31, k16 = koff & 15;
                    int jj   = ((koff >> 4) << 2) | ((k16 >> 3) << 1) | (k16 & 1);
                    int tig  = (k16 & 7) >> 1;
                    int lane2 = ((b & 7) << 2) | tig;
                    size_t idx = ((size_t)((p >> 5) * 4 + (b >> 3)) * 32 + lane2) * 8 + jj;
                    __half hv = __float2half(v);
                    Tf_hi[nxt][idx] = hv;
                    Tf_lo[nxt][idx] = __float2half((v - __half2float(hv)) * LO_SCALE);
                }
            }

            grid_sync(++ns * NB);   // theta_{t+1} published
        }
    } else {
        // ================================ MLP =================================
        const int bat = (cta - NCTA_MV) * 16 + w;
        float x_prev = 0.f;

        for (int t = 0; t < SEQ; ++t) {
            const int cur = t & 1;
            const float* th = theta_f[cur] + (size_t)bat * P_PAD;
            float tt = (float)t * (1.0f / (float)SEQ);

            float z = tt * __ldcg(th + lane) + __ldcg(th + 32 + lane);
            float y = z / (1.f + expf(-z));
#pragma unroll
            for (int L = 0; L < 4; ++L) {
                const float* Wb = th + 64 + L * 1056;
                const float4* rp = (const float4*)(Wb + lane * 32);
                float4 wr[8];
#pragma unroll
                for (int j = 0; j < 8; ++j) wr[j] = __ldcg(rp + j);
                float acc = __ldcg(Wb + 1024 + lane);
#pragma unroll
                for (int j = 0; j < 8; ++j) {
                    acc += __shfl_sync(0xffffffffu, y, 4*j + 0) * wr[j].x;
                    acc += __shfl_sync(0xffffffffu, y, 4*j + 1) * wr[j].y;
                    acc += __shfl_sync(0xffffffffu, y, 4*j + 2) * wr[j].z;
                    acc += __shfl_sync(0xffffffffu, y, 4*j + 3) * wr[j].w;
                }
                y = acc / (1.f + expf(-acc));
            }
            const float* Wf = th + 4288;
            float pm = y * __ldcg(Wf + lane);
            float pv = y * __ldcg(Wf + 32 + lane);
#pragma unroll
            for (int off = 16; off; off >>= 1) {
                pm += __shfl_xor_sync(0xffffffffu, pm, off);
                pv += __shfl_xor_sync(0xffffffffu, pv, off);
            }
            if (lane == 0) {
                float meanv = tanhf(pm + __ldcg(Wf + 64));
                float lv = pv + __ldcg(Wf + 65);
                lv = fminf(4.f, fmaxf(-4.f, lv));
                float stdv = expf(0.5f * lv);
                out[bat * SEQ + t] = meanv;
                out[BATCH * SEQ + bat * SEQ + t] = stdv;
                float x_t = (t < inf_start)
                    ? __ldg(xs + bat * SEQ + t)
                    : fmaf(__ldg(noise + t * BATCH + bat), stdv, meanv);
                dx_g[bat] = x_t - x_prev;
                x_prev = x_t;
            }

            // publish dx: intra-CTA barrier orders the 16 lane-0 stores, then
            // one release-increment of the flag per MLP CTA
            __syncthreads();
            if (tid == 0) {
                unsigned* fp = &mlp_flag;
                asm volatile("red.release.gpu.global.add.u32 [%0], 1;"
                             :: "l"(fp) : "memory");
            }

            if (t == SEQ - 1) break;
            grid_sync(++ns * NB);
        }
    }
    // no final barrier: out[] writes are CTA-private; kernel exit is the
    // rendezvous. Counters are reset by reset_kernel at next launch.
}

// ---------------------------------------------------------------------------
extern "C" void kernel_launch(void* const* d_in, const int* in_sizes, int n_in,
                              void* d_out, int out_size) {
    const float* xs         = (const float*)d_in[0];
    const float* noise      = (const float*)d_in[1];
    const float* theta_init = (const float*)d_in[2];
    const float* A          = (const float*)d_in[3];
    const float* Bv         = (const float*)d_in[4];
    const int*   p_is       = (n_in > 5) ? (const int*)d_in[5] : nullptr;
    const int    has_is     = (n_in > 5) ? 1 : 0;

    reset_kernel<<<1, 32>>>();
    main_kernel<<<NCTA, THREADS>>>(xs, noise, theta_init, A, Bv, p_is, has_is,
                                   (float*)d_out);
}